// round 11
// baseline (speedup 1.0000x reference)
#include <cuda_runtime.h>
#include <cstddef>

#define FULL_MASK 0xffffffffu

// ---------------------------------------------------------------------------
// packed fp32x2 FMA (sm_100+)
// ---------------------------------------------------------------------------
__device__ __forceinline__ float2 ffma2(float2 a, float2 b, float2 c) {
    unsigned long long ua = *reinterpret_cast<unsigned long long*>(&a);
    unsigned long long ub = *reinterpret_cast<unsigned long long*>(&b);
    unsigned long long uc = *reinterpret_cast<unsigned long long*>(&c);
    unsigned long long ud;
    asm("fma.rn.f32x2 %0, %1, %2, %3;" : "=l"(ud) : "l"(ua), "l"(ub), "l"(uc));
    return *reinterpret_cast<float2*>(&ud);
}

// L2-coherent accessors for intra-kernel producer/consumer data.
__device__ __forceinline__ float ldcg(const float* p) {
    float v; asm volatile("ld.global.cg.f32 %0, [%1];" : "=f"(v) : "l"(p)); return v;
}
__device__ __forceinline__ float2 ldcg2(const float2* p) {
    float2 v;
    asm volatile("ld.global.cg.v2.f32 {%0,%1}, [%2];" : "=f"(v.x), "=f"(v.y) : "l"(p));
    return v;
}
__device__ __forceinline__ int ldcg_i(const int* p) {
    int v; asm volatile("ld.global.cg.s32 %0, [%1];" : "=r"(v) : "l"(p)); return v;
}
__device__ __forceinline__ void stcg(float* p, float v) {
    asm volatile("st.global.cg.f32 [%0], %1;" :: "l"(p), "f"(v));
}

__device__ __forceinline__ float sigf(float x) {
    return __fdividef(1.0f, 1.0f + __expf(-x));
}
__device__ __forceinline__ float tanh_fast(float x) {
    return 2.0f * sigf(2.0f * x) - 1.0f;
}

// Scratch
__device__ float g_xg[64 * 1024 * 256];      // layer-1 input gates (64 MB)
__device__ float g_h2[64 * 1024 * 64];       // h2 stream scan->tail (16 MB)
// flags[0..511]: GEMM m-tile (batch*8+chunk), ready at 2
// flags[512+b] : h2 stream progress for batch b (= number of steps published)
__device__ int g_flag[576];

// ---------------------------------------------------------------------------
// Fused kernel. blockIdx.x < 64    -> scan CTA (one batch, L1/L2, 2 phases/step)
//               blockIdx.x < 72    -> tail CTA (8 warps, one batch each: L3/L4/FC)
//               blockIdx.x >= 72   -> GEMM CTA (chunk-major tile order)
// ---------------------------------------------------------------------------
__global__ __launch_bounds__(256, 1) void fused_kernel(
    const float* __restrict__ X,
    const float* __restrict__ w1_ih0, const float* __restrict__ w1_hh0,
    const float* __restrict__ b1_0,
    const float* __restrict__ w1_ih1, const float* __restrict__ w1_hh1,
    const float* __restrict__ b1_1,
    const float* __restrict__ w2_ih0, const float* __restrict__ w2_hh0,
    const float* __restrict__ b2_0,
    const float* __restrict__ w2_ih1, const float* __restrict__ w2_hh1,
    const float* __restrict__ b2_1,
    const float* __restrict__ fc_w,  const float* __restrict__ fc_b,
    float* __restrict__ out)
{
    // ================= GEMM branch =================
    if (blockIdx.x >= 72) {
        __shared__ float As[16][132];
        __shared__ float Bs[16][132];
        const int gi = blockIdx.x - 72;          // 0..1023
        const int xnt = gi & 1;
        const int r  = gi >> 1;
        const int chunk = r >> 6;                // chunk-major order
        const int batch = r & 63;
        const int y  = batch * 8 + chunk;
        const int m0 = y * 128;
        const int n0 = xnt * 128;
        const int tid = threadIdx.x;
        const int tx = tid & 15;
        const int ty = tid >> 4;

        float2 c[8][4];
#pragma unroll
        for (int i = 0; i < 8; i++)
#pragma unroll
            for (int j = 0; j < 4; j++) c[i][j] = make_float2(0.f, 0.f);

        for (int k0 = 0; k0 < 512; k0 += 16) {
#pragma unroll
            for (int i = 0; i < 2; i++) {
                int idx = tid + i * 256;
                int row = idx >> 2;
                int kq  = (idx & 3) << 2;
                float4 va = *reinterpret_cast<const float4*>(&X[(size_t)(m0 + row) * 512 + k0 + kq]);
                As[kq + 0][row] = va.x; As[kq + 1][row] = va.y;
                As[kq + 2][row] = va.z; As[kq + 3][row] = va.w;
                float4 vb = *reinterpret_cast<const float4*>(&w1_ih0[(size_t)(n0 + row) * 512 + k0 + kq]);
                Bs[kq + 0][row] = vb.x; Bs[kq + 1][row] = vb.y;
                Bs[kq + 2][row] = vb.z; Bs[kq + 3][row] = vb.w;
            }
            __syncthreads();
#pragma unroll
            for (int kk = 0; kk < 16; kk++) {
                float4 a0 = *reinterpret_cast<const float4*>(&As[kk][ty * 8]);
                float4 a1 = *reinterpret_cast<const float4*>(&As[kk][ty * 8 + 4]);
                float4 b0 = *reinterpret_cast<const float4*>(&Bs[kk][tx * 8]);
                float4 b1 = *reinterpret_cast<const float4*>(&Bs[kk][tx * 8 + 4]);
                float  a[8]  = {a0.x, a0.y, a0.z, a0.w, a1.x, a1.y, a1.z, a1.w};
                float2 b2[4] = {make_float2(b0.x, b0.y), make_float2(b0.z, b0.w),
                                make_float2(b1.x, b1.y), make_float2(b1.z, b1.w)};
#pragma unroll
                for (int i = 0; i < 8; i++) {
                    float2 aa = make_float2(a[i], a[i]);
#pragma unroll
                    for (int j = 0; j < 4; j++)
                        c[i][j] = ffma2(aa, b2[j], c[i][j]);
                }
            }
            __syncthreads();
        }

        float4 bv0 = *reinterpret_cast<const float4*>(&b1_0[n0 + tx * 8]);
        float4 bv1 = *reinterpret_cast<const float4*>(&b1_0[n0 + tx * 8 + 4]);
#pragma unroll
        for (int i = 0; i < 8; i++) {
            int m = m0 + ty * 8 + i;
            float4 o0 = make_float4(c[i][0].x + bv0.x, c[i][0].y + bv0.y,
                                    c[i][1].x + bv0.z, c[i][1].y + bv0.w);
            float4 o1 = make_float4(c[i][2].x + bv1.x, c[i][2].y + bv1.y,
                                    c[i][3].x + bv1.z, c[i][3].y + bv1.w);
            *reinterpret_cast<float4*>(&g_xg[(size_t)m * 256 + n0 + tx * 8])     = o0;
            *reinterpret_cast<float4*>(&g_xg[(size_t)m * 256 + n0 + tx * 8 + 4]) = o1;
        }
        __syncthreads();
        if (tid == 0) {
            __threadfence();
            atomicAdd(&g_flag[y], 1);
        }
        return;
    }

    // ================= tail branch: L3/L4/FC, one batch per warp =================
    if (blockIdx.x >= 64) {
        __shared__ float2 tw_ih0[32 * 32];      // [k2][lane], lane<24 valid
        __shared__ float  tw_hh0[6 * 32];       // [k][lane]
        __shared__ float  tw_ih1[6 * 32];
        __shared__ float  tw_hh1[6 * 32];
        __shared__ float  tfcw[36];
        __shared__ float  tb20[32];
        __shared__ float  tb21[32];
        __shared__ float  tfcb[8];
        __shared__ float  th3[8][8];
        __shared__ float  th4[8][8];
        __shared__ float2 th2[8][32];

        const int t = threadIdx.x;
        for (int i = t; i < 1024; i += 256) {
            int k2 = i >> 5, l = i & 31;
            tw_ih0[i] = (l < 24)
                ? make_float2(w2_ih0[l * 64 + 2 * k2], w2_ih0[l * 64 + 2 * k2 + 1])
                : make_float2(0.f, 0.f);
        }
        if (t < 192) {
            int k = t / 32, l = t & 31;
            tw_hh0[t] = (l < 24) ? w2_hh0[l * 6 + k] : 0.f;
            tw_ih1[t] = (l < 24) ? w2_ih1[l * 6 + k] : 0.f;
            tw_hh1[t] = (l < 24) ? w2_hh1[l * 6 + k] : 0.f;
        }
        if (t < 36) tfcw[t] = fc_w[t];
        if (t < 32) { tb20[t] = (t < 24) ? b2_0[t] : 0.f;
                      tb21[t] = (t < 24) ? b2_1[t] : 0.f; }
        if (t < 8)  tfcb[t] = (t < 6) ? fc_b[t] : 0.f;
        if (t < 64) { th3[t >> 3][t & 7] = 0.f; th4[t >> 3][t & 7] = 0.f; }
        __syncthreads();

        const int w = t >> 5;                 // warp -> batch slot
        const int l = t & 31;
        const int b = (blockIdx.x - 64) * 8 + w;
        const int* flg = &g_flag[512 + b];
        float c3 = 0.f, c4 = 0.f;
        float* outp = out + ((size_t)b << 10) * 6;

        for (int s = 0; s < 1024; s++) {
            // acquire h2(s) (published in batches of 8 steps)
            while (ldcg_i(flg) < s + 1) __nanosleep(100);
            __threadfence();
            th2[w][l] = ldcg2(reinterpret_cast<const float2*>(
                                 &g_h2[((size_t)b * 1024 + s) * 64]) + l);
            __syncwarp();

            // L3: gates[24] = b2_0 + W2ih0 @ h2 + W2hh0 @ h3
            const float2* h2p = th2[w];
            float2 a0 = make_float2(0.f, 0.f), a1 = make_float2(0.f, 0.f);
#pragma unroll
            for (int k2 = 0; k2 < 32; k2 += 2) {
                a0 = ffma2(tw_ih0[k2 * 32 + l],       h2p[k2],     a0);
                a1 = ffma2(tw_ih0[(k2 + 1) * 32 + l], h2p[k2 + 1], a1);
            }
            float acc = a0.x + a0.y + a1.x + a1.y + tb20[l];
#pragma unroll
            for (int k = 0; k < 6; k++) acc += tw_hh0[k * 32 + l] * th3[w][k];
            float vf = __shfl_sync(FULL_MASK, acc, (l + 6) & 31);
            float vg = __shfl_sync(FULL_MASK, acc, (l + 12) & 31);
            float vo = __shfl_sync(FULL_MASK, acc, (l + 18) & 31);
            if (l < 6) {
                float gi = sigf(acc), gf = sigf(vf);
                float gg = tanh_fast(vg), go = sigf(vo);
                c3 = gf * c3 + gi * gg;
                th3[w][l] = go * tanh_fast(c3);
            }
            __syncwarp();
            // L4
            float acc4 = tb21[l];
#pragma unroll
            for (int k = 0; k < 6; k++) {
                acc4 += tw_ih1[k * 32 + l] * th3[w][k];
                acc4 += tw_hh1[k * 32 + l] * th4[w][k];
            }
            float wf = __shfl_sync(FULL_MASK, acc4, (l + 6) & 31);
            float wg = __shfl_sync(FULL_MASK, acc4, (l + 12) & 31);
            float wo = __shfl_sync(FULL_MASK, acc4, (l + 18) & 31);
            __syncwarp();
            if (l < 6) {
                float gi = sigf(acc4), gf = sigf(wf);
                float gg = tanh_fast(wg), go = sigf(wo);
                c4 = gf * c4 + gi * gg;
                th4[w][l] = go * tanh_fast(c4);
            }
            __syncwarp();
            if (l < 6) {
                float o = tfcb[l];
#pragma unroll
                for (int k = 0; k < 6; k++) o += tfcw[l * 6 + k] * th4[w][k];
                outp[(size_t)s * 6 + l] = o;
            }
        }
        return;
    }

    // ================= scan branch: 2 phases, 2 barriers per step =================
    // A(k): pre1(k+1) = Whh0@h1(k) + xg(k+1);  pre2(k) = Wih1@h1(k) + Whh1@h2(k-1) + b
    // B(k): warps 0-1: h1(k+1)=cell1(pre1);  warps 2-3: h2(k)=cell2(pre2) + stream out
    __shared__ float sh_h1[64];
    __shared__ float sh_h2[64];
    __shared__ float sh_pre1[256];
    __shared__ float sh_pre2[256];

    const int t = threadIdx.x;
    const int b = blockIdx.x;
    const int yb = b * 8;

    float2 wA[32], wB[32], wC[32];
    {
        const float2* pa = reinterpret_cast<const float2*>(w1_hh0) + t * 32;
        const float2* pb = reinterpret_cast<const float2*>(w1_ih1) + t * 32;
        const float2* pc = reinterpret_cast<const float2*>(w1_hh1) + t * 32;
#pragma unroll
        for (int i = 0; i < 32; i++) { wA[i] = pa[i]; wB[i] = pb[i]; wC[i] = pc[i]; }
    }
    const float bias11 = b1_1[t];

    if (t < 64) { sh_h1[t] = 0.f; sh_h2[t] = 0.f; }

    // wait for chunk 0
    if (t == 0) {
        while (atomicAdd(&g_flag[yb], 0) < 2) __nanosleep(64);
        __threadfence();
    }
    __syncthreads();

    float c1 = 0.f, c2 = 0.f;
    const float* xg = g_xg + ((size_t)b << 10) * 256;

    // ---- prologue: h1(0) = cell1(xg(0)) ----
    {
        float xg0 = ldcg(&xg[t]);
        sh_pre1[t] = xg0;
    }
    __syncthreads();
    if (t < 64) {
        float gi = sigf(sh_pre1[t]);
        float gf = sigf(sh_pre1[64 + t]);
        float gg = tanh_fast(sh_pre1[128 + t]);
        float go = sigf(sh_pre1[192 + t]);
        c1 = gf * c1 + gi * gg;
        sh_h1[t] = go * tanh_fast(c1);
    }
    __syncthreads();
    float xg_next = ldcg(&xg[256 + t]);      // row 1

    for (int k = 0; k < 1024; k++) {
        float xg_cur = xg_next;              // = xg(k+1); stale at k=1023 (dead value)
        if (k + 2 < 1024) {
            if (((k + 2) & 127) == 0) {      // entering a new chunk at row k+2
                if (t == 0) {
                    int yc = yb + ((k + 2) >> 7);
                    while (atomicAdd(&g_flag[yc], 0) < 2) __nanosleep(64);
                    __threadfence();
                }
                __syncthreads();
            }
            xg_next = ldcg(&xg[(size_t)(k + 2) * 256 + t]);
        }

        // ---- phase A: 3 dots, shared h1 loads ----
        {
            float2 aA0 = make_float2(0.f, 0.f), aA1 = aA0;
            float2 aB0 = aA0, aB1 = aA0, aC0 = aA0, aC1 = aA0;
            const float4* h1p = reinterpret_cast<const float4*>(sh_h1);
            const float4* h2p = reinterpret_cast<const float4*>(sh_h2);
#pragma unroll
            for (int k4 = 0; k4 < 16; k4++) {
                float4 hv = h1p[k4];
                float2 lo = make_float2(hv.x, hv.y);
                float2 hi = make_float2(hv.z, hv.w);
                aA0 = ffma2(wA[2 * k4],     lo, aA0);
                aA1 = ffma2(wA[2 * k4 + 1], hi, aA1);
                aB0 = ffma2(wB[2 * k4],     lo, aB0);
                aB1 = ffma2(wB[2 * k4 + 1], hi, aB1);
                float4 gv = h2p[k4];
                float2 lo2 = make_float2(gv.x, gv.y);
                float2 hi2 = make_float2(gv.z, gv.w);
                aC0 = ffma2(wC[2 * k4],     lo2, aC0);
                aC1 = ffma2(wC[2 * k4 + 1], hi2, aC1);
            }
            sh_pre1[t] = (aA0.x + aA0.y) + (aA1.x + aA1.y) + xg_cur;
            sh_pre2[t] = ((aB0.x + aB0.y) + (aB1.x + aB1.y))
                       + ((aC0.x + aC0.y) + (aC1.x + aC1.y)) + bias11;
        }
        __syncthreads();   // SA

        // ---- phase B: both cells in parallel + stream publish on idle warp ----
        if (t < 64) {
            float gi = sigf(sh_pre1[t]);
            float gf = sigf(sh_pre1[64 + t]);
            float gg = tanh_fast(sh_pre1[128 + t]);
            float go = sigf(sh_pre1[192 + t]);
            c1 = gf * c1 + gi * gg;
            sh_h1[t] = go * tanh_fast(c1);
        } else if (t < 128) {
            const int e = t - 64;
            float gi = sigf(sh_pre2[e]);
            float gf = sigf(sh_pre2[64 + e]);
            float gg = tanh_fast(sh_pre2[128 + e]);
            float go = sigf(sh_pre2[192 + e]);
            c2 = gf * c2 + gi * gg;
            float h2n = go * tanh_fast(c2);
            sh_h2[e] = h2n;
            stcg(&g_h2[((size_t)b * 1024 + k) * 64 + e], h2n);
        } else if (t == 128 && k > 0 && (k & 7) == 0) {
            // publish h2 steps [0, k) (stores barrier-ordered from B(k-1) and earlier)
            __threadfence();
            atomicMax(&g_flag[512 + b], k);
        }
        __syncthreads();   // SB
    }
    if (t == 0) {
        __threadfence();
        atomicMax(&g_flag[512 + b], 1024);
    }
}

// ---------------------------------------------------------------------------
extern "C" void kernel_launch(void* const* d_in, const int* in_sizes, int n_in,
                              void* d_out, int out_size) {
    const float* x      = (const float*)d_in[0];
    const float* w1_ih0 = (const float*)d_in[1];
    const float* w1_hh0 = (const float*)d_in[2];
    const float* b1_0   = (const float*)d_in[3];
    const float* w1_ih1 = (const float*)d_in[4];
    const float* w1_hh1 = (const float*)d_in[5];
    const float* b1_1   = (const float*)d_in[6];
    const float* w2_ih0 = (const float*)d_in[7];
    const float* w2_hh0 = (const float*)d_in[8];
    const float* b2_0   = (const float*)d_in[9];
    const float* w2_ih1 = (const float*)d_in[10];
    const float* w2_hh1 = (const float*)d_in[11];
    const float* b2_1   = (const float*)d_in[12];
    const float* fc_w   = (const float*)d_in[13];
    const float* fc_b   = (const float*)d_in[14];
    float* out = (float*)d_out;

    // reset completion flags (graph-capturable memset node)
    void* flag_ptr = nullptr;
    cudaGetSymbolAddress(&flag_ptr, g_flag);
    cudaMemsetAsync(flag_ptr, 0, 576 * sizeof(int));

    fused_kernel<<<72 + 1024, 256>>>(x, w1_ih0, w1_hh0, b1_0,
                                     w1_ih1, w1_hh1, b1_1,
                                     w2_ih0, w2_hh0, b2_0,
                                     w2_ih1, w2_hh1, b2_1,
                                     fc_w, fc_b, out);
}